// round 12
// baseline (speedup 1.0000x reference)
#include <cuda_runtime.h>
#include <cuda_bf16.h>
#include <cstdint>

#define NN 8192
#define CCH 256
#define DDH 128

// scratch (allocation-free: device globals)
__device__ __nv_bfloat16 g_fib[(size_t)NN*DDH];   // fi bf16, K-major [N][128]
__device__ __nv_bfloat16 g_fjb[(size_t)NN*DDH];   // fj bf16, K-major [N][128]
__device__ __nv_bfloat16 g_fkT[(size_t)DDH*NN];   // fk^T bf16 [128][N]
__device__ float g_t[(size_t)NN*DDH];             // attention output fp32
__device__ __nv_bfloat16 g_Wt[3*128*256];         // W feat-part, bf16, [p][n][k]

__device__ __forceinline__ float sigf(float x){
    float t, h = 0.5f * x;
    asm("tanh.approx.f32 %0, %1;" : "=f"(t) : "f"(h));
    return fmaf(0.5f, t, 0.5f);
}
__device__ __forceinline__ uint32_t pack_bf2(float lo, float hi){
    __nv_bfloat162 h = __float22bfloat162_rn(make_float2(lo, hi));
    return *(uint32_t*)&h;
}
// D += A(16x16,row) * B(16x8,col), bf16 in, f32 acc  (baseline PTX, sm_80+)
__device__ __forceinline__ void mma16816(float* c, uint32_t a0, uint32_t a1, uint32_t a2, uint32_t a3,
                                         uint32_t b0, uint32_t b1){
    asm volatile("mma.sync.aligned.m16n8k16.row.col.f32.bf16.bf16.f32 "
        "{%0,%1,%2,%3}, {%4,%5,%6,%7}, {%8,%9}, {%0,%1,%2,%3};"
        : "+f"(c[0]), "+f"(c[1]), "+f"(c[2]), "+f"(c[3])
        : "r"(a0), "r"(a1), "r"(a2), "r"(a3), "r"(b0), "r"(b1));
}
__device__ __forceinline__ void ldsm4(uint32_t* r, uint32_t addr){
    asm volatile("ldmatrix.sync.aligned.m8n8.x4.shared.b16 {%0,%1,%2,%3}, [%4];"
        : "=r"(r[0]), "=r"(r[1]), "=r"(r[2]), "=r"(r[3]) : "r"(addr));
}
__device__ __forceinline__ uint32_t smem_u32(const void* p){
    uint32_t a;
    asm("{ .reg .u64 t; cvta.to.shared.u64 t, %1; cvt.u32.u64 %0, t; }" : "=r"(a) : "l"(p));
    return a;
}
__device__ __forceinline__ void cpa16(uint32_t dst, const void* src){
    asm volatile("cp.async.cg.shared.global [%0], [%1], 16;" :: "r"(dst), "l"(src));
}
#define CPA_COMMIT() asm volatile("cp.async.commit_group;" ::: "memory")
#define CPA_WAIT0()  asm volatile("cp.async.wait_group 0;" ::: "memory")

// ---------------------------------------------------------------------------
// Stage 0: W -> bf16 [n][k] transpose (feat rows 3..258 only).  grid 3 x 256
// ---------------------------------------------------------------------------
__global__ void __launch_bounds__(256)
transp_w(const float* __restrict__ Wi, const float* __restrict__ Wj,
         const float* __restrict__ Wk)
{
    const float* W = (blockIdx.x == 0) ? Wi : (blockIdx.x == 1) ? Wj : Wk;
    __nv_bfloat16* dst = g_Wt + blockIdx.x * 32768;
    for (int i = threadIdx.x; i < 32768; i += 256) {
        int n = i & 127, kk = i >> 7;
        dst[n*256 + kk] = __float2bfloat16(W[(kk + 3)*128 + n]);
    }
}

// ---------------------------------------------------------------------------
// Stage 1: projections on mma.sync. grid (128,3) x 256 (8 warps = 4wr x 2wc).
// Per CTA: 64 rows x 128 cols. K=256 feat (bf16 mma) + 3 lm cols (fp32 init).
// ---------------------------------------------------------------------------
#define PPIT 136
#define PROJ_SMEM ((64*PPIT + 128*PPIT)*2 + 4*128*4)

__global__ void __launch_bounds__(256)
proj_kernel(const float* __restrict__ lm,
            const float* __restrict__ feat,
            const float* __restrict__ Wi, const float* __restrict__ bi,
            const float* __restrict__ Wj, const float* __restrict__ bj,
            const float* __restrict__ Wk, const float* __restrict__ bk)
{
    extern __shared__ __nv_bfloat16 sp[];
    __nv_bfloat16* s_x = sp;               // [64][136] bf16
    __nv_bfloat16* s_w = sp + 64*PPIT;     // [128][136] bf16
    float* s_bw = (float*)(sp + 64*PPIT + 128*PPIT);  // [4][128]: W rows 0..2, bias

    const int p = blockIdx.y;
    const float* W; const float* b;
    if (p == 0)      { W = Wi; b = bi; }
    else if (p == 1) { W = Wj; b = bj; }
    else             { W = Wk; b = bk; }

    const int tid  = threadIdx.x;
    const int w    = tid >> 5;
    const int lane = tid & 31;
    const int wr   = w >> 1, wc = w & 1;
    const int g    = lane >> 3;   // unused for addr; kept for clarity
    const int gq   = lane >> 2, t = lane & 3;
    const int l15  = lane & 15;
    const int l16h = (lane >> 4) & 1;
    const int row0 = blockIdx.x * 64;

    // preload bias + lm-rows of W
    for (int i = tid; i < 512; i += 256) {
        int rr = i >> 7, c = i & 127;
        s_bw[i] = (rr < 3) ? W[rr*128 + c] : b[c];
    }
    __syncthreads();

    // fp32 init: bias + lm @ W[0:3]
    const int r0 = row0 + wr*16 + gq;
    const int r1 = r0 + 8;
    float lm0[3], lm1[3];
    #pragma unroll
    for (int k = 0; k < 3; ++k) { lm0[k] = lm[r0*3 + k]; lm1[k] = lm[r1*3 + k]; }

    float acc[8][4];
    #pragma unroll
    for (int nt = 0; nt < 8; ++nt) {
        const int c = wc*64 + nt*8 + t*2;
        float a0 = s_bw[384 + c],     a1 = s_bw[384 + c + 1];
        float a2 = a0, a3 = a1;
        #pragma unroll
        for (int k = 0; k < 3; ++k) {
            float w0 = s_bw[k*128 + c], w1 = s_bw[k*128 + c + 1];
            a0 = fmaf(lm0[k], w0, a0); a1 = fmaf(lm0[k], w1, a1);
            a2 = fmaf(lm1[k], w0, a2); a3 = fmaf(lm1[k], w1, a3);
        }
        acc[nt][0] = a0; acc[nt][1] = a1; acc[nt][2] = a2; acc[nt][3] = a3;
    }

    const uint32_t sxu = smem_u32(s_x);
    const uint32_t swu = smem_u32(s_w);
    const uint32_t a_base = sxu + (uint32_t)((wr*16 + l15)*PPIT + 8*l16h)*2;
    const uint32_t b_base = swu + (uint32_t)((wc*64 + l15)*PPIT + 8*l16h)*2;
    const __nv_bfloat16* Wt = g_Wt + p*32768;

    for (int kc = 0; kc < 256; kc += 128) {
        __syncthreads();
        // x chunk: fp32 -> bf16, 64 rows x 128 k
        #pragma unroll
        for (int s = 0; s < 8; ++s) {
            int i = tid + s*256;
            int r = i >> 5, q = i & 31;
            float4 f = *(const float4*)(feat + (size_t)(row0 + r)*CCH + kc + q*4);
            uint2 u; u.x = pack_bf2(f.x, f.y); u.y = pack_bf2(f.z, f.w);
            *(uint2*)(s_x + r*PPIT + q*4) = u;
        }
        // W chunk: bf16 direct, 128 n x 128 k
        #pragma unroll
        for (int s = 0; s < 8; ++s) {
            int i = tid + s*256;
            int n = i >> 4, m = i & 15;
            *(uint4*)(s_w + n*PPIT + m*8) = *(const uint4*)(Wt + n*256 + kc + m*8);
        }
        __syncthreads();

        #pragma unroll
        for (int ks = 0; ks < 8; ++ks) {
            uint32_t a[4];
            ldsm4(a, a_base + ks*32);
            #pragma unroll
            for (int ntp = 0; ntp < 4; ++ntp) {
                uint32_t bq[4];
                ldsm4(bq, b_base + (uint32_t)(ntp*16*PPIT)*2 + ks*32);
                mma16816(acc[2*ntp],     a[0], a[1], a[2], a[3], bq[0], bq[2]);
                mma16816(acc[2*ntp + 1], a[0], a[1], a[2], a[3], bq[1], bq[3]);
            }
        }
    }

    if (p < 2) {
        __nv_bfloat16* outb = (p == 0) ? g_fib : g_fjb;
        #pragma unroll
        for (int nt = 0; nt < 8; ++nt) {
            const int c = wc*64 + nt*8 + t*2;
            *(uint32_t*)(outb + (size_t)r0*DDH + c) = pack_bf2(acc[nt][0], acc[nt][1]);
            *(uint32_t*)(outb + (size_t)r1*DDH + c) = pack_bf2(acc[nt][2], acc[nt][3]);
        }
    } else {
        #pragma unroll
        for (int nt = 0; nt < 8; ++nt) {
            const int c = wc*64 + nt*8 + t*2;
            g_fkT[(size_t)c*NN + r0]       = __float2bfloat16(acc[nt][0]);
            g_fkT[(size_t)(c + 1)*NN + r0] = __float2bfloat16(acc[nt][1]);
            g_fkT[(size_t)c*NN + r1]       = __float2bfloat16(acc[nt][2]);
            g_fkT[(size_t)(c + 1)*NN + r1] = __float2bfloat16(acc[nt][3]);
        }
    }
}

// ---------------------------------------------------------------------------
// Stage 2: flash attention, mma.sync m16n8k16 bf16, register-resident P,
// ldmatrix fragment loads, cp.async double buffer.
// grid 128 x 256 threads (8 warps = 4 row-groups x 2 col-groups).
// ---------------------------------------------------------------------------
#define PIT 136
#define OFF_FI 0
#define OFF_FJ (64*PIT)
#define OFF_FK (64*PIT + 2*128*PIT)
#define ATTN_SMEM ((64*PIT + 4*128*PIT) * 2)

__device__ __forceinline__ void load_tile_async(uint32_t fj_u, uint32_t fk_u, int jt, int tid){
    const __nv_bfloat16* fj = g_fjb + (size_t)jt*128*DDH;
    #pragma unroll
    for (int s = 0; s < 8; ++s) {
        int i = tid + s*256;
        int r = i >> 4, c8 = i & 15;
        cpa16(fj_u + (uint32_t)(r*PIT + c8*8)*2, fj + r*DDH + c8*8);
    }
    #pragma unroll
    for (int s = 0; s < 8; ++s) {
        int i = tid + s*256;
        int r = i >> 4, c8 = i & 15;          // r = d, c8*8 = j offset
        cpa16(fk_u + (uint32_t)(r*PIT + c8*8)*2, g_fkT + (size_t)r*NN + jt*128 + c8*8);
    }
}

__global__ void __launch_bounds__(256)
attn_kernel()
{
    extern __shared__ __nv_bfloat16 sb[];
    const int tid  = threadIdx.x;
    const int w    = tid >> 5;
    const int lane = tid & 31;
    const int wr   = w >> 1, wc = w & 1;
    const int g    = lane >> 2, t = lane & 3;
    const int l15  = lane & 15;
    const int l16h = (lane >> 4) & 1;
    const int row0 = blockIdx.x * 64;
    const int arow = wr*16 + g;

    __nv_bfloat16* s_fi = sb + OFF_FI;
    const uint32_t sbu = smem_u32(sb);
    const uint32_t fj_u0 = sbu + OFF_FJ*2, fj_u1 = sbu + (OFF_FJ + 128*PIT)*2;
    const uint32_t fk_u0 = sbu + OFF_FK*2, fk_u1 = sbu + (OFF_FK + 128*PIT)*2;

    // fi tile [64][128] (plain loads)
    for (int i = tid; i < 1024; i += 256) {
        int r = i >> 4, c8 = i & 15;
        *(uint4*)(s_fi + r*PIT + c8*8) =
            *(const uint4*)(g_fib + (size_t)(row0 + r)*DDH + c8*8);
    }
    // prefetch tile 0
    load_tile_async(fj_u0, fk_u0, 0, tid);
    CPA_COMMIT();

    // ldmatrix per-thread base offsets (bytes)
    const uint32_t aA = sbu + (uint32_t)((wr*16 + l15)*PIT + 8*l16h)*2;           // fi
    const uint32_t oB1 = (uint32_t)((wc*64 + l15)*PIT + 8*l16h)*2;                // fj (+buf base)
    const uint32_t oB2 = (uint32_t)(l15*PIT + wc*64 + 8*l16h)*2;                  // fk (+buf base)

    float acc[16][4];
    #pragma unroll
    for (int nt = 0; nt < 16; ++nt)
        #pragma unroll
        for (int q = 0; q < 4; ++q) acc[nt][q] = 0.f;
    float rs_lo = 0.f, rs_hi = 0.f;

    for (int jt = 0; jt < NN/128; ++jt) {
        const int buf = jt & 1;
        CPA_WAIT0();
        __syncthreads();                       // tile jt visible; prev compute done
        if (jt + 1 < NN/128) {
            load_tile_async(buf ? fj_u0 : fj_u1, buf ? fk_u0 : fk_u1, jt + 1, tid);
            CPA_COMMIT();
        }
        const uint32_t bB1 = (buf ? fj_u1 : fj_u0) + oB1;
        const uint32_t bB2 = (buf ? fk_u1 : fk_u0) + oB2;

        // ---- S = fi @ fj^T : rows wr*16..+16, j-cols wc*64..+64 ----
        float sc[8][4];
        #pragma unroll
        for (int nt = 0; nt < 8; ++nt)
            #pragma unroll
            for (int q = 0; q < 4; ++q) sc[nt][q] = 0.f;

        #pragma unroll
        for (int ks = 0; ks < 8; ++ks) {
            uint32_t a[4];
            ldsm4(a, aA + ks*32);
            #pragma unroll
            for (int ntp = 0; ntp < 4; ++ntp) {
                uint32_t bq[4];
                ldsm4(bq, bB1 + (uint32_t)(ntp*16*PIT)*2 + ks*32);
                mma16816(sc[2*ntp],     a[0], a[1], a[2], a[3], bq[0], bq[2]);
                mma16816(sc[2*ntp + 1], a[0], a[1], a[2], a[3], bq[1], bq[3]);
            }
        }

        // ---- sigmoid in regs -> rowsum + PV A-fragments (no smem) ----
        uint32_t pa[4][4];
        #pragma unroll
        for (int nt = 0; nt < 8; ++nt) {
            float v0 = sigf(sc[nt][0]);
            float v1 = sigf(sc[nt][1]);
            float v2 = sigf(sc[nt][2]);
            float v3 = sigf(sc[nt][3]);
            rs_lo += v0 + v1;
            rs_hi += v2 + v3;
            const int k2 = nt >> 1;
            if (nt & 1) { pa[k2][2] = pack_bf2(v0, v1); pa[k2][3] = pack_bf2(v2, v3); }
            else        { pa[k2][0] = pack_bf2(v0, v1); pa[k2][1] = pack_bf2(v2, v3); }
        }

        // ---- acc += P @ fk over this warp's j-half, all 128 d-cols ----
        #pragma unroll
        for (int ks = 0; ks < 4; ++ks) {
            #pragma unroll
            for (int ntp = 0; ntp < 8; ++ntp) {
                uint32_t bq[4];
                ldsm4(bq, bB2 + (uint32_t)(ntp*16*PIT)*2 + ks*32);
                mma16816(acc[2*ntp],     pa[ks][0], pa[ks][1], pa[ks][2], pa[ks][3], bq[0], bq[2]);
                mma16816(acc[2*ntp + 1], pa[ks][0], pa[ks][1], pa[ks][2], pa[ks][3], bq[1], bq[3]);
            }
        }
    }

    // rowsum: reduce over the 4 t-lanes sharing each row
    rs_lo += __shfl_xor_sync(0xffffffffu, rs_lo, 1);
    rs_lo += __shfl_xor_sync(0xffffffffu, rs_lo, 2);
    rs_hi += __shfl_xor_sync(0xffffffffu, rs_hi, 1);
    rs_hi += __shfl_xor_sync(0xffffffffu, rs_hi, 2);

    // cross-wc reduction of acc + rowsum (reuse tile smem)
    float* s_red = (float*)(sb + OFF_FJ);     // [64][130] fp32
    float* s_rs  = (float*)(sb + OFF_FK);     // [2][64]
    __syncthreads();
    if (t == 0) {
        s_rs[wc*64 + arow]     = rs_lo;
        s_rs[wc*64 + arow + 8] = rs_hi;
    }
    if (wc == 0) {
        #pragma unroll
        for (int nt = 0; nt < 16; ++nt) {
            *(float2*)(s_red + arow*130 + nt*8 + t*2)       = make_float2(acc[nt][0], acc[nt][1]);
            *(float2*)(s_red + (arow + 8)*130 + nt*8 + t*2) = make_float2(acc[nt][2], acc[nt][3]);
        }
    }
    __syncthreads();
    if (wc == 1) {
        const float inv_lo = 1.0f / (s_rs[arow]     + rs_lo);
        const float inv_hi = 1.0f / (s_rs[arow + 8] + rs_hi);
        float* o0 = g_t + (size_t)(row0 + arow)*DDH;
        float* o1 = g_t + (size_t)(row0 + arow + 8)*DDH;
        #pragma unroll
        for (int nt = 0; nt < 16; ++nt) {
            const int c = nt*8 + t*2;
            float2 p0 = *(float2*)(s_red + arow*130 + c);
            float2 p1 = *(float2*)(s_red + (arow + 8)*130 + c);
            *(float2*)(o0 + c) = make_float2((acc[nt][0] + p0.x)*inv_lo, (acc[nt][1] + p0.y)*inv_lo);
            *(float2*)(o1 + c) = make_float2((acc[nt][2] + p1.x)*inv_hi, (acc[nt][3] + p1.y)*inv_hi);
        }
    }
}

// ---------------------------------------------------------------------------
// Stage 3: out = features + t @ Wr + br    grid 256 x 256 threads
// ---------------------------------------------------------------------------
#define FMA4(A, S, F) do { (A).x += (S)*(F).x; (A).y += (S)*(F).y; (A).z += (S)*(F).z; (A).w += (S)*(F).w; } while(0)

__global__ void __launch_bounds__(256)
out_kernel(const float* __restrict__ feat,
           const float* __restrict__ Wr,
           const float* __restrict__ br,
           float* __restrict__ out)
{
    __shared__ float s_t[32*132];
    const int tid = threadIdx.x;
    const int tx = tid & 15, ty = tid >> 4;
    const int row0 = blockIdx.x * 32;

    for (int i = tid; i < 32*32; i += 256) {
        int r = i >> 5, c4 = i & 31;
        *(float4*)(s_t + r*132 + c4*4) =
            *(const float4*)(g_t + (size_t)(row0 + r)*DDH + c4*4);
    }

    float4 acc[2][4];
    #pragma unroll
    for (int rr = 0; rr < 2; ++rr)
        #pragma unroll
        for (int h = 0; h < 4; ++h) acc[rr][h] = make_float4(0.f, 0.f, 0.f, 0.f);

    __syncthreads();

    #pragma unroll 4
    for (int k = 0; k < DDH; ++k) {
        float4 w[4];
        #pragma unroll
        for (int h = 0; h < 4; ++h)
            w[h] = *(const float4*)(Wr + k*CCH + tx*4 + 64*h);
        float t0 = s_t[ty*132 + k];
        float t1 = s_t[(ty + 16)*132 + k];
        #pragma unroll
        for (int h = 0; h < 4; ++h) {
            FMA4(acc[0][h], t0, w[h]);
            FMA4(acc[1][h], t1, w[h]);
        }
    }

    #pragma unroll
    for (int rr = 0; rr < 2; ++rr) {
        int r = row0 + ty + 16*rr;
        #pragma unroll
        for (int h = 0; h < 4; ++h) {
            int c = tx*4 + 64*h;
            float4 bv = *(const float4*)(br + c);
            float4 fv = *(const float4*)(feat + (size_t)r*CCH + c);
            float4 o  = acc[rr][h];
            o.x += bv.x + fv.x; o.y += bv.y + fv.y;
            o.z += bv.z + fv.z; o.w += bv.w + fv.w;
            *(float4*)(out + (size_t)r*CCH + c) = o;
        }
    }
}

// ---------------------------------------------------------------------------
extern "C" void kernel_launch(void* const* d_in, const int* in_sizes, int n_in,
                              void* d_out, int out_size)
{
    const float* lm   = (const float*)d_in[0];
    const float* feat = (const float*)d_in[1];
    const float* Wi   = (const float*)d_in[2];
    const float* bi   = (const float*)d_in[3];
    const float* Wj   = (const float*)d_in[4];
    const float* bj   = (const float*)d_in[5];
    const float* Wk   = (const float*)d_in[6];
    const float* bk   = (const float*)d_in[7];
    const float* Wr   = (const float*)d_in[8];
    const float* br   = (const float*)d_in[9];
    float* out = (float*)d_out;

    cudaFuncSetAttribute(proj_kernel, cudaFuncAttributeMaxDynamicSharedMemorySize, PROJ_SMEM);
    cudaFuncSetAttribute(attn_kernel, cudaFuncAttributeMaxDynamicSharedMemorySize, ATTN_SMEM);

    transp_w<<<3, 256>>>(Wi, Wj, Wk);
    proj_kernel<<<dim3(NN/64, 3), 256, PROJ_SMEM>>>(lm, feat, Wi, bi, Wj, bj, Wk, bk);
    attn_kernel<<<NN/64, 256, ATTN_SMEM>>>();
    out_kernel<<<NN/32, 256>>>(feat, Wr, br, out);
}

// round 14
// speedup vs baseline: 1.2118x; 1.2118x over previous
#include <cuda_runtime.h>
#include <cuda_bf16.h>
#include <cstdint>

#define NN 8192
#define CCH 256
#define DDH 128

// scratch (allocation-free: device globals)
__device__ __nv_bfloat16 g_fib[(size_t)NN*DDH];   // fi bf16, K-major [N][128]
__device__ __nv_bfloat16 g_fjb[(size_t)NN*DDH];   // fj bf16, K-major [N][128]
__device__ __nv_bfloat16 g_fkT[(size_t)DDH*NN];   // fk^T bf16 [128][N]
__device__ float g_t[(size_t)NN*DDH];             // attention output fp32
__device__ __nv_bfloat16 g_Wt[3*128*256];         // W feat-part, bf16, [p][n][k]
__device__ __nv_bfloat16 g_WrT[256*128];          // Wr^T bf16 [n=256][k=128]

__device__ __forceinline__ float sigf(float x){
    float t, h = 0.5f * x;
    asm("tanh.approx.f32 %0, %1;" : "=f"(t) : "f"(h));
    return fmaf(0.5f, t, 0.5f);
}
__device__ __forceinline__ uint32_t pack_bf2(float lo, float hi){
    __nv_bfloat162 h = __float22bfloat162_rn(make_float2(lo, hi));
    return *(uint32_t*)&h;
}
// D += A(16x16,row) * B(16x8,col), bf16 in, f32 acc  (baseline PTX, sm_80+)
__device__ __forceinline__ void mma16816(float* c, uint32_t a0, uint32_t a1, uint32_t a2, uint32_t a3,
                                         uint32_t b0, uint32_t b1){
    asm volatile("mma.sync.aligned.m16n8k16.row.col.f32.bf16.bf16.f32 "
        "{%0,%1,%2,%3}, {%4,%5,%6,%7}, {%8,%9}, {%0,%1,%2,%3};"
        : "+f"(c[0]), "+f"(c[1]), "+f"(c[2]), "+f"(c[3])
        : "r"(a0), "r"(a1), "r"(a2), "r"(a3), "r"(b0), "r"(b1));
}
__device__ __forceinline__ void ldsm4(uint32_t* r, uint32_t addr){
    asm volatile("ldmatrix.sync.aligned.m8n8.x4.shared.b16 {%0,%1,%2,%3}, [%4];"
        : "=r"(r[0]), "=r"(r[1]), "=r"(r[2]), "=r"(r[3]) : "r"(addr));
}
__device__ __forceinline__ uint32_t smem_u32(const void* p){
    uint32_t a;
    asm("{ .reg .u64 t; cvta.to.shared.u64 t, %1; cvt.u32.u64 %0, t; }" : "=r"(a) : "l"(p));
    return a;
}
__device__ __forceinline__ void cpa16(uint32_t dst, const void* src){
    asm volatile("cp.async.cg.shared.global [%0], [%1], 16;" :: "r"(dst), "l"(src));
}
#define CPA_COMMIT() asm volatile("cp.async.commit_group;" ::: "memory")
#define CPA_WAIT0()  asm volatile("cp.async.wait_group 0;" ::: "memory")

// ---------------------------------------------------------------------------
// Stage 0: weight transposes to bf16.  grid 4 x 256
//   p<3 : Wi/Wj/Wk feat rows -> g_Wt[p] as [n=128][k=256]
//   p==3: Wr [128][256] -> g_WrT [n=256][k=128]
// ---------------------------------------------------------------------------
__global__ void __launch_bounds__(256)
transp_w(const float* __restrict__ Wi, const float* __restrict__ Wj,
         const float* __restrict__ Wk, const float* __restrict__ Wr)
{
    const int p = blockIdx.x;
    if (p < 3) {
        const float* W = (p == 0) ? Wi : (p == 1) ? Wj : Wk;
        __nv_bfloat16* dst = g_Wt + p * 32768;
        for (int i = threadIdx.x; i < 32768; i += 256) {
            int n = i & 127, kk = i >> 7;
            dst[n*256 + kk] = __float2bfloat16(W[(kk + 3)*128 + n]);
        }
    } else {
        for (int i = threadIdx.x; i < 32768; i += 256) {
            int n = i >> 7, kk = i & 127;
            g_WrT[n*128 + kk] = __float2bfloat16(Wr[kk*256 + n]);
        }
    }
}

// ---------------------------------------------------------------------------
// Stage 1: projections on mma.sync. grid (128,3) x 256 (8 warps = 4wr x 2wc).
// Per CTA: 64 rows x 128 cols. K=256 feat (bf16 mma) + 3 lm cols (fp32 init).
// ---------------------------------------------------------------------------
#define PPIT 136
#define PROJ_SMEM ((64*PPIT + 128*PPIT)*2 + 4*128*4)

__global__ void __launch_bounds__(256)
proj_kernel(const float* __restrict__ lm,
            const float* __restrict__ feat,
            const float* __restrict__ Wi, const float* __restrict__ bi,
            const float* __restrict__ Wj, const float* __restrict__ bj,
            const float* __restrict__ Wk, const float* __restrict__ bk)
{
    extern __shared__ __nv_bfloat16 sp[];
    __nv_bfloat16* s_x = sp;               // [64][136] bf16
    __nv_bfloat16* s_w = sp + 64*PPIT;     // [128][136] bf16
    float* s_bw = (float*)(sp + 64*PPIT + 128*PPIT);  // [4][128]: W rows 0..2, bias

    const int p = blockIdx.y;
    const float* W; const float* b;
    if (p == 0)      { W = Wi; b = bi; }
    else if (p == 1) { W = Wj; b = bj; }
    else             { W = Wk; b = bk; }

    const int tid  = threadIdx.x;
    const int w    = tid >> 5;
    const int lane = tid & 31;
    const int wr   = w >> 1, wc = w & 1;
    const int gq   = lane >> 2, t = lane & 3;
    const int l15  = lane & 15;
    const int l16h = (lane >> 4) & 1;
    const int row0 = blockIdx.x * 64;

    // preload bias + lm-rows of W
    for (int i = tid; i < 512; i += 256) {
        int rr = i >> 7, c = i & 127;
        s_bw[i] = (rr < 3) ? W[rr*128 + c] : b[c];
    }
    __syncthreads();

    // fp32 init: bias + lm @ W[0:3]
    const int r0 = row0 + wr*16 + gq;
    const int r1 = r0 + 8;
    float lm0[3], lm1[3];
    #pragma unroll
    for (int k = 0; k < 3; ++k) { lm0[k] = lm[r0*3 + k]; lm1[k] = lm[r1*3 + k]; }

    float acc[8][4];
    #pragma unroll
    for (int nt = 0; nt < 8; ++nt) {
        const int c = wc*64 + nt*8 + t*2;
        float a0 = s_bw[384 + c],     a1 = s_bw[384 + c + 1];
        float a2 = a0, a3 = a1;
        #pragma unroll
        for (int k = 0; k < 3; ++k) {
            float w0 = s_bw[k*128 + c], w1 = s_bw[k*128 + c + 1];
            a0 = fmaf(lm0[k], w0, a0); a1 = fmaf(lm0[k], w1, a1);
            a2 = fmaf(lm1[k], w0, a2); a3 = fmaf(lm1[k], w1, a3);
        }
        acc[nt][0] = a0; acc[nt][1] = a1; acc[nt][2] = a2; acc[nt][3] = a3;
    }

    const uint32_t sxu = smem_u32(s_x);
    const uint32_t swu = smem_u32(s_w);
    const uint32_t a_base = sxu + (uint32_t)((wr*16 + l15)*PPIT + 8*l16h)*2;
    const uint32_t b_base = swu + (uint32_t)((wc*64 + l15)*PPIT + 8*l16h)*2;
    const __nv_bfloat16* Wt = g_Wt + p*32768;

    for (int kc = 0; kc < 256; kc += 128) {
        __syncthreads();
        // x chunk: fp32 -> bf16, 64 rows x 128 k
        #pragma unroll
        for (int s = 0; s < 8; ++s) {
            int i = tid + s*256;
            int r = i >> 5, q = i & 31;
            float4 f = *(const float4*)(feat + (size_t)(row0 + r)*CCH + kc + q*4);
            uint2 u; u.x = pack_bf2(f.x, f.y); u.y = pack_bf2(f.z, f.w);
            *(uint2*)(s_x + r*PPIT + q*4) = u;
        }
        // W chunk: bf16 direct, 128 n x 128 k
        #pragma unroll
        for (int s = 0; s < 8; ++s) {
            int i = tid + s*256;
            int n = i >> 4, m = i & 15;
            *(uint4*)(s_w + n*PPIT + m*8) = *(const uint4*)(Wt + n*256 + kc + m*8);
        }
        __syncthreads();

        #pragma unroll
        for (int ks = 0; ks < 8; ++ks) {
            uint32_t a[4];
            ldsm4(a, a_base + ks*32);
            #pragma unroll
            for (int ntp = 0; ntp < 4; ++ntp) {
                uint32_t bq[4];
                ldsm4(bq, b_base + (uint32_t)(ntp*16*PPIT)*2 + ks*32);
                mma16816(acc[2*ntp],     a[0], a[1], a[2], a[3], bq[0], bq[2]);
                mma16816(acc[2*ntp + 1], a[0], a[1], a[2], a[3], bq[1], bq[3]);
            }
        }
    }

    if (p < 2) {
        __nv_bfloat16* outb = (p == 0) ? g_fib : g_fjb;
        #pragma unroll
        for (int nt = 0; nt < 8; ++nt) {
            const int c = wc*64 + nt*8 + t*2;
            *(uint32_t*)(outb + (size_t)r0*DDH + c) = pack_bf2(acc[nt][0], acc[nt][1]);
            *(uint32_t*)(outb + (size_t)r1*DDH + c) = pack_bf2(acc[nt][2], acc[nt][3]);
        }
    } else {
        #pragma unroll
        for (int nt = 0; nt < 8; ++nt) {
            const int c = wc*64 + nt*8 + t*2;
            g_fkT[(size_t)c*NN + r0]       = __float2bfloat16(acc[nt][0]);
            g_fkT[(size_t)(c + 1)*NN + r0] = __float2bfloat16(acc[nt][1]);
            g_fkT[(size_t)c*NN + r1]       = __float2bfloat16(acc[nt][2]);
            g_fkT[(size_t)(c + 1)*NN + r1] = __float2bfloat16(acc[nt][3]);
        }
    }
}

// ---------------------------------------------------------------------------
// Stage 2: flash attention (R8-proven): mma.sync, register-resident P,
// manual LDS fragment loads, cp.async double buffer.
// grid 128 x 256 threads (8 warps = 4 row-groups x 2 col-groups).
// ---------------------------------------------------------------------------
#define PIT 136
#define OFF_FI 0
#define OFF_FJ (64*PIT)
#define OFF_FK (64*PIT + 2*128*PIT)
#define ATTN_SMEM ((64*PIT + 4*128*PIT) * 2)

__device__ __forceinline__ void load_tile_async(uint32_t fj_u, uint32_t fk_u, int jt, int tid){
    const __nv_bfloat16* fj = g_fjb + (size_t)jt*128*DDH;
    #pragma unroll
    for (int s = 0; s < 8; ++s) {
        int i = tid + s*256;
        int r = i >> 4, c8 = i & 15;
        cpa16(fj_u + (uint32_t)(r*PIT + c8*8)*2, fj + r*DDH + c8*8);
    }
    #pragma unroll
    for (int s = 0; s < 8; ++s) {
        int i = tid + s*256;
        int r = i >> 4, c8 = i & 15;          // r = d, c8*8 = j offset
        cpa16(fk_u + (uint32_t)(r*PIT + c8*8)*2, g_fkT + (size_t)r*NN + jt*128 + c8*8);
    }
}

__global__ void __launch_bounds__(256)
attn_kernel()
{
    extern __shared__ __nv_bfloat16 sb[];
    const int tid  = threadIdx.x;
    const int w    = tid >> 5;
    const int lane = tid & 31;
    const int wr   = w >> 1, wc = w & 1;
    const int g    = lane >> 2, t = lane & 3;
    const int row0 = blockIdx.x * 64;
    const int arow = wr*16 + g;

    __nv_bfloat16* s_fi = sb + OFF_FI;
    const uint32_t sbu = smem_u32(sb);
    const uint32_t fj_u0 = sbu + OFF_FJ*2, fj_u1 = sbu + (OFF_FJ + 128*PIT)*2;
    const uint32_t fk_u0 = sbu + OFF_FK*2, fk_u1 = sbu + (OFF_FK + 128*PIT)*2;

    // fi tile [64][128] (plain loads)
    for (int i = tid; i < 1024; i += 256) {
        int r = i >> 4, c8 = i & 15;
        *(uint4*)(s_fi + r*PIT + c8*8) =
            *(const uint4*)(g_fib + (size_t)(row0 + r)*DDH + c8*8);
    }
    // prefetch tile 0
    load_tile_async(fj_u0, fk_u0, 0, tid);
    CPA_COMMIT();

    float acc[16][4];
    #pragma unroll
    for (int nt = 0; nt < 16; ++nt)
        #pragma unroll
        for (int q = 0; q < 4; ++q) acc[nt][q] = 0.f;
    float rs_lo = 0.f, rs_hi = 0.f;

    for (int jt = 0; jt < NN/128; ++jt) {
        const int buf = jt & 1;
        CPA_WAIT0();
        __syncthreads();                       // tile jt visible; prev compute done
        if (jt + 1 < NN/128) {
            load_tile_async(buf ? fj_u0 : fj_u1, buf ? fk_u0 : fk_u1, jt + 1, tid);
            CPA_COMMIT();
        }
        __nv_bfloat16* s_fj = sb + OFF_FJ + buf*128*PIT;
        __nv_bfloat16* s_fk = sb + OFF_FK + buf*128*PIT;

        // ---- S = fi @ fj^T : rows wr*16..+16, j-cols wc*64..+64 ----
        float sc[8][4];
        #pragma unroll
        for (int nt = 0; nt < 8; ++nt)
            #pragma unroll
            for (int q = 0; q < 4; ++q) sc[nt][q] = 0.f;

        #pragma unroll
        for (int ks = 0; ks < 8; ++ks) {
            const int kc = ks*16 + t*2;
            uint32_t a0 = *(const uint32_t*)(s_fi + arow*PIT + kc);
            uint32_t a1 = *(const uint32_t*)(s_fi + (arow + 8)*PIT + kc);
            uint32_t a2 = *(const uint32_t*)(s_fi + arow*PIT + kc + 8);
            uint32_t a3 = *(const uint32_t*)(s_fi + (arow + 8)*PIT + kc + 8);
            #pragma unroll
            for (int nt = 0; nt < 8; ++nt) {
                const int jrow = wc*64 + nt*8 + g;
                uint32_t b0 = *(const uint32_t*)(s_fj + jrow*PIT + kc);
                uint32_t b1 = *(const uint32_t*)(s_fj + jrow*PIT + kc + 8);
                mma16816(sc[nt], a0, a1, a2, a3, b0, b1);
            }
        }

        // ---- sigmoid in regs -> rowsum + PV A-fragments (no smem) ----
        uint32_t pa[4][4];
        #pragma unroll
        for (int nt = 0; nt < 8; ++nt) {
            float v0 = sigf(sc[nt][0]);
            float v1 = sigf(sc[nt][1]);
            float v2 = sigf(sc[nt][2]);
            float v3 = sigf(sc[nt][3]);
            rs_lo += v0 + v1;
            rs_hi += v2 + v3;
            const int k2 = nt >> 1;
            if (nt & 1) { pa[k2][2] = pack_bf2(v0, v1); pa[k2][3] = pack_bf2(v2, v3); }
            else        { pa[k2][0] = pack_bf2(v0, v1); pa[k2][1] = pack_bf2(v2, v3); }
        }

        // ---- acc += P @ fk over this warp's j-half, all 128 d-cols ----
        #pragma unroll
        for (int ks = 0; ks < 4; ++ks) {
            const int kc = wc*64 + ks*16 + t*2;
            #pragma unroll
            for (int nt = 0; nt < 16; ++nt) {
                const int drow = nt*8 + g;
                uint32_t b0 = *(const uint32_t*)(s_fk + drow*PIT + kc);
                uint32_t b1 = *(const uint32_t*)(s_fk + drow*PIT + kc + 8);
                mma16816(acc[nt], pa[ks][0], pa[ks][1], pa[ks][2], pa[ks][3], b0, b1);
            }
        }
    }

    // rowsum: reduce over the 4 t-lanes sharing each row
    rs_lo += __shfl_xor_sync(0xffffffffu, rs_lo, 1);
    rs_lo += __shfl_xor_sync(0xffffffffu, rs_lo, 2);
    rs_hi += __shfl_xor_sync(0xffffffffu, rs_hi, 1);
    rs_hi += __shfl_xor_sync(0xffffffffu, rs_hi, 2);

    // cross-wc reduction of acc + rowsum (reuse tile smem)
    float* s_red = (float*)(sb + OFF_FJ);     // [64][130] fp32
    float* s_rs  = (float*)(sb + OFF_FK);     // [2][64]
    __syncthreads();
    if (t == 0) {
        s_rs[wc*64 + arow]     = rs_lo;
        s_rs[wc*64 + arow + 8] = rs_hi;
    }
    if (wc == 0) {
        #pragma unroll
        for (int nt = 0; nt < 16; ++nt) {
            *(float2*)(s_red + arow*130 + nt*8 + t*2)       = make_float2(acc[nt][0], acc[nt][1]);
            *(float2*)(s_red + (arow + 8)*130 + nt*8 + t*2) = make_float2(acc[nt][2], acc[nt][3]);
        }
    }
    __syncthreads();
    if (wc == 1) {
        const float inv_lo = 1.0f / (s_rs[arow]     + rs_lo);
        const float inv_hi = 1.0f / (s_rs[arow + 8] + rs_hi);
        float* o0 = g_t + (size_t)(row0 + arow)*DDH;
        float* o1 = g_t + (size_t)(row0 + arow + 8)*DDH;
        #pragma unroll
        for (int nt = 0; nt < 16; ++nt) {
            const int c = nt*8 + t*2;
            float2 p0 = *(float2*)(s_red + arow*130 + c);
            float2 p1 = *(float2*)(s_red + (arow + 8)*130 + c);
            *(float2*)(o0 + c) = make_float2((acc[nt][0] + p0.x)*inv_lo, (acc[nt][1] + p0.y)*inv_lo);
            *(float2*)(o1 + c) = make_float2((acc[nt][2] + p1.x)*inv_hi, (acc[nt][3] + p1.y)*inv_hi);
        }
    }
}

// ---------------------------------------------------------------------------
// Stage 3: out = features + t @ Wr + br on mma.sync.
// grid 128 x 256 threads (8 warps = 4wr x 2wc). 64 rows/CTA, n=256 (wc*128),
// K=128 single pass. t cvt to bf16 in smem; WrT staged bf16.
// ---------------------------------------------------------------------------
#define OPIT 136
#define OUT_SMEM ((64*OPIT + 256*OPIT) * 2)

__global__ void __launch_bounds__(256)
out_kernel(const float* __restrict__ feat,
           const float* __restrict__ br,
           float* __restrict__ out)
{
    extern __shared__ __nv_bfloat16 so[];
    __nv_bfloat16* s_t = so;               // [64][136]
    __nv_bfloat16* s_w = so + 64*OPIT;     // [256][136]

    const int tid  = threadIdx.x;
    const int w    = tid >> 5;
    const int lane = tid & 31;
    const int wr   = w >> 1, wc = w & 1;
    const int g    = lane >> 2, t = lane & 3;
    const int l15  = lane & 15;
    const int l16h = (lane >> 4) & 1;
    const int row0 = blockIdx.x * 64;

    // stage t (fp32 -> bf16): 64 rows x 128
    #pragma unroll
    for (int s = 0; s < 8; ++s) {
        int i = tid + s*256;
        int r = i >> 5, q = i & 31;
        float4 f = *(const float4*)(g_t + (size_t)(row0 + r)*DDH + q*4);
        uint2 u; u.x = pack_bf2(f.x, f.y); u.y = pack_bf2(f.z, f.w);
        *(uint2*)(s_t + r*OPIT + q*4) = u;
    }
    // stage WrT: 256 n x 128 k
    #pragma unroll
    for (int s = 0; s < 16; ++s) {
        int i = tid + s*256;
        int n = i >> 4, m = i & 15;
        *(uint4*)(s_w + n*OPIT + m*8) = *(const uint4*)(g_WrT + n*128 + m*8);
    }
    __syncthreads();

    const uint32_t stu = smem_u32(s_t);
    const uint32_t swu = smem_u32(s_w);
    const uint32_t a_base = stu + (uint32_t)((wr*16 + l15)*OPIT + 8*l16h)*2;
    const uint32_t b_base = swu + (uint32_t)((wc*128 + l15)*OPIT + 8*l16h)*2;

    float acc[16][4];
    #pragma unroll
    for (int nt = 0; nt < 16; ++nt)
        #pragma unroll
        for (int q = 0; q < 4; ++q) acc[nt][q] = 0.f;

    #pragma unroll
    for (int ks = 0; ks < 8; ++ks) {
        uint32_t a[4];
        ldsm4(a, a_base + ks*32);
        #pragma unroll
        for (int ntp = 0; ntp < 8; ++ntp) {
            uint32_t bq[4];
            ldsm4(bq, b_base + (uint32_t)(ntp*16*OPIT)*2 + ks*32);
            mma16816(acc[2*ntp],     a[0], a[1], a[2], a[3], bq[0], bq[2]);
            mma16816(acc[2*ntp + 1], a[0], a[1], a[2], a[3], bq[1], bq[3]);
        }
    }

    // epilogue: + br + features (fp32)
    const int r0 = row0 + wr*16 + g;
    const int r1 = r0 + 8;
    #pragma unroll
    for (int nt = 0; nt < 16; ++nt) {
        const int c = wc*128 + nt*8 + t*2;
        float2 bv = *(const float2*)(br + c);
        float2 f0 = *(const float2*)(feat + (size_t)r0*CCH + c);
        float2 f1 = *(const float2*)(feat + (size_t)r1*CCH + c);
        *(float2*)(out + (size_t)r0*CCH + c) =
            make_float2(acc[nt][0] + bv.x + f0.x, acc[nt][1] + bv.y + f0.y);
        *(float2*)(out + (size_t)r1*CCH + c) =
            make_float2(acc[nt][2] + bv.x + f1.x, acc[nt][3] + bv.y + f1.y);
    }
}

// ---------------------------------------------------------------------------
extern "C" void kernel_launch(void* const* d_in, const int* in_sizes, int n_in,
                              void* d_out, int out_size)
{
    const float* lm   = (const float*)d_in[0];
    const float* feat = (const float*)d_in[1];
    const float* Wi   = (const float*)d_in[2];
    const float* bi   = (const float*)d_in[3];
    const float* Wj   = (const float*)d_in[4];
    const float* bj   = (const float*)d_in[5];
    const float* Wk   = (const float*)d_in[6];
    const float* bk   = (const float*)d_in[7];
    const float* Wr   = (const float*)d_in[8];
    const float* br   = (const float*)d_in[9];
    float* out = (float*)d_out;

    cudaFuncSetAttribute(proj_kernel, cudaFuncAttributeMaxDynamicSharedMemorySize, PROJ_SMEM);
    cudaFuncSetAttribute(attn_kernel, cudaFuncAttributeMaxDynamicSharedMemorySize, ATTN_SMEM);
    cudaFuncSetAttribute(out_kernel,  cudaFuncAttributeMaxDynamicSharedMemorySize, OUT_SMEM);

    transp_w<<<4, 256>>>(Wi, Wj, Wk, Wr);
    proj_kernel<<<dim3(NN/64, 3), 256, PROJ_SMEM>>>(lm, feat, Wi, bi, Wj, bj, Wk, bk);
    attn_kernel<<<NN/64, 256, ATTN_SMEM>>>();
    out_kernel<<<NN/64, 256, OUT_SMEM>>>(feat, br, out);
}